// round 1
// baseline (speedup 1.0000x reference)
#include <cuda_runtime.h>

// Problem constants
#define BB   4
#define SS   2048
#define DD   512
#define HH   8
#define HD   64
#define NTOK (BB*SS)          // 8192
#define QKV_N (3*DD)          // 1536
#define SCALE 0.125f          // HD^-0.5

// ---------------- scratch (__device__ globals; no runtime alloc allowed) ----
static __device__ float g_q[BB*HH*SS*HD];              // 16 MB, SCALE pre-applied
static __device__ float g_k[BB*HH*SS*HD];              // 16 MB
static __device__ float g_v[BB*HH*SS*HD];              // 16 MB
static __device__ float g_sc[134217728];               // [B][H][S][S] 512 MB
static __device__ float g_ao[NTOK*DD];                 // 16 MB

// ============================================================================
// Kernel 1: QKV GEMM.  C[m,n] = sum_k x[m,k] * w_qkv[n,k]
// 64x64 tile, 256 threads, 4x4 frags, vectorized over contiguous K dim.
// Epilogue scatters into g_q/g_k/g_v [B][H][S][hd], scaling Q by SCALE.
// ============================================================================
__global__ __launch_bounds__(256) void k_qkv(const float* __restrict__ x,
                                             const float* __restrict__ w) {
    __shared__ float As[64][68];
    __shared__ float Bs[64][68];
    const int tid = threadIdx.x;
    const int tx = tid & 15, ty = tid >> 4;
    const int m0 = blockIdx.y * 64;
    const int n0 = blockIdx.x * 64;

    float c[4][4] = {};
    for (int k0 = 0; k0 < DD; k0 += 64) {
        for (int f = tid; f < 1024; f += 256) {
            int r = f >> 4, cq = (f & 15) << 2;
            *(float4*)&As[r][cq] = *(const float4*)&x[(size_t)(m0 + r) * DD + k0 + cq];
            *(float4*)&Bs[r][cq] = *(const float4*)&w[(size_t)(n0 + r) * DD + k0 + cq];
        }
        __syncthreads();
        #pragma unroll
        for (int kk = 0; kk < 64; kk += 4) {
            float4 a[4], b4[4];
            #pragma unroll
            for (int i = 0; i < 4; i++) a[i]  = *(float4*)&As[ty*4+i][kk];
            #pragma unroll
            for (int j = 0; j < 4; j++) b4[j] = *(float4*)&Bs[tx*4+j][kk];
            #pragma unroll
            for (int i = 0; i < 4; i++)
                #pragma unroll
                for (int j = 0; j < 4; j++)
                    c[i][j] += a[i].x*b4[j].x + a[i].y*b4[j].y
                             + a[i].z*b4[j].z + a[i].w*b4[j].w;
        }
        __syncthreads();
    }
    // epilogue: n0 is a multiple of 64 -> whole tile is one (which, h) block
    const int which = n0 >> 9;          // 0=q 1=k 2=v
    const int h     = (n0 >> 6) & 7;
    const int b     = m0 / SS;
    const int sbase = m0 % SS;
    float* dst = (which == 0) ? g_q : (which == 1) ? g_k : g_v;
    const float mul = (which == 0) ? SCALE : 1.0f;
    #pragma unroll
    for (int i = 0; i < 4; i++) {
        int srow = sbase + ty*4 + i;
        float4 o;
        o.x = c[i][0]*mul; o.y = c[i][1]*mul; o.z = c[i][2]*mul; o.w = c[i][3]*mul;
        *(float4*)&dst[(((size_t)b*HH + h)*SS + srow)*HD + tx*4] = o;
    }
}

// ============================================================================
// Kernel 2: scores + pre-softmax talking-heads mix (fused).
// CTA = (b, q-tile64, k-tile64). Loops over all 8 heads, computes S_h tile,
// accumulates mixed_g += w_l[g,h] * S_h in registers (8 x 4x4 per thread).
// Writes mixed scores (+b_l) to g_sc[b][g][q][k].
// ============================================================================
__global__ __launch_bounds__(256, 1) void k_scores(const float* __restrict__ wl,
                                                   const float* __restrict__ bl) {
    __shared__ float Qs[64][68];
    __shared__ float Ks[64][68];
    __shared__ float s_wl[8][8];
    __shared__ float s_bl[8];
    const int tid = threadIdx.x;
    const int tx = tid & 15, ty = tid >> 4;
    const int kt = blockIdx.x * 64;
    const int qt = blockIdx.y * 64;
    const int b  = blockIdx.z;

    if (tid < 64) s_wl[tid >> 3][tid & 7] = wl[tid];
    if (tid < 8)  s_bl[tid] = bl[tid];

    float acc[8][16];
    #pragma unroll
    for (int g = 0; g < 8; g++)
        #pragma unroll
        for (int e = 0; e < 16; e++) acc[g][e] = 0.f;

    for (int h = 0; h < 8; h++) {
        __syncthreads();   // protect smem (and publishes s_wl/s_bl on h==0)
        const float* qp = &g_q[(((size_t)b*HH + h)*SS + qt)*HD];
        const float* kp = &g_k[(((size_t)b*HH + h)*SS + kt)*HD];
        for (int f = tid; f < 1024; f += 256) {
            int r = f >> 4, cq = (f & 15) << 2;
            *(float4*)&Qs[r][cq] = *(const float4*)&qp[(size_t)r*HD + cq];
            *(float4*)&Ks[r][cq] = *(const float4*)&kp[(size_t)r*HD + cq];
        }
        __syncthreads();
        float s[4][4] = {};
        #pragma unroll
        for (int kk = 0; kk < 64; kk += 4) {
            float4 a[4], b4[4];
            #pragma unroll
            for (int i = 0; i < 4; i++) a[i]  = *(float4*)&Qs[ty*4+i][kk];
            #pragma unroll
            for (int j = 0; j < 4; j++) b4[j] = *(float4*)&Ks[tx*4+j][kk];
            #pragma unroll
            for (int i = 0; i < 4; i++)
                #pragma unroll
                for (int j = 0; j < 4; j++)
                    s[i][j] += a[i].x*b4[j].x + a[i].y*b4[j].y
                             + a[i].z*b4[j].z + a[i].w*b4[j].w;
        }
        #pragma unroll
        for (int g = 0; g < 8; g++) {
            float wv = s_wl[g][h];
            #pragma unroll
            for (int i = 0; i < 4; i++)
                #pragma unroll
                for (int j = 0; j < 4; j++)
                    acc[g][i*4+j] += wv * s[i][j];
        }
    }
    // epilogue: + b_l, store 8 mixed tiles
    #pragma unroll
    for (int g = 0; g < 8; g++) {
        float blv = s_bl[g];
        size_t base = ((size_t)b*HH + g)*SS;
        #pragma unroll
        for (int i = 0; i < 4; i++) {
            int q = qt + ty*4 + i;
            float4 o;
            o.x = acc[g][i*4+0] + blv;
            o.y = acc[g][i*4+1] + blv;
            o.z = acc[g][i*4+2] + blv;
            o.w = acc[g][i*4+3] + blv;
            *(float4*)&g_sc[(base + q)*SS + kt + tx*4] = o;
        }
    }
}

// ============================================================================
// Kernel 3: softmax + post-softmax talking-heads mix (fused, in-place).
// CTA = (b, q). 8 warps; warp w softmaxes head w's 2048-row in smem, then all
// threads mix across heads with w_w (+b_w) and write back to g_sc[b][g][q][:].
// Dynamic smem: 8*2048*4 = 64 KB.
// ============================================================================
__global__ __launch_bounds__(256) void k_softmax(const float* __restrict__ ww,
                                                 const float* __restrict__ bw) {
    extern __shared__ float sm[];        // [8][2048]
    __shared__ float inv_l[8];
    __shared__ float s_ww[8][8];
    __shared__ float s_bw[8];
    const int tid = threadIdx.x;
    const int b = blockIdx.x >> 11;
    const int q = blockIdx.x & 2047;

    if (tid < 64) s_ww[tid >> 3][tid & 7] = ww[tid];
    if (tid < 8)  s_bw[tid] = bw[tid];

    const size_t rowbase = (size_t)b*HH*SS*SS + (size_t)q*SS;
    for (int f = tid; f < 8*512; f += 256) {
        int h = f >> 9, c4 = (f & 511) << 2;
        *(float4*)&sm[h*SS + c4] = *(const float4*)&g_sc[rowbase + (size_t)h*SS*SS + c4];
    }
    __syncthreads();

    {
        const int h = tid >> 5, lane = tid & 31;
        float m = -1e30f;
        for (int i = lane; i < SS; i += 32) m = fmaxf(m, sm[h*SS + i]);
        #pragma unroll
        for (int o = 16; o; o >>= 1) m = fmaxf(m, __shfl_xor_sync(0xffffffffu, m, o));
        float l = 0.f;
        for (int i = lane; i < SS; i += 32) {
            float e = __expf(sm[h*SS + i] - m);
            sm[h*SS + i] = e;
            l += e;
        }
        #pragma unroll
        for (int o = 16; o; o >>= 1) l += __shfl_xor_sync(0xffffffffu, l, o);
        if (lane == 0) inv_l[h] = 1.0f / l;
    }
    __syncthreads();

    for (int i = tid; i < SS; i += 256) {
        float p[8];
        #pragma unroll
        for (int h = 0; h < 8; h++) p[h] = sm[h*SS + i] * inv_l[h];
        #pragma unroll
        for (int g = 0; g < 8; g++) {
            float o = s_bw[g];
            #pragma unroll
            for (int h = 0; h < 8; h++) o += s_ww[g][h] * p[h];
            g_sc[rowbase + (size_t)g*SS*SS + i] = o;
        }
    }
}

// ============================================================================
// Kernel 4: AV GEMM per (b, h, q-tile).  out[q, d] = sum_k P[q,k] * V[k,d]
// 64x64 out tile, K-loop over 2048. Writes g_ao[b][s][h*64+d].
// ============================================================================
__global__ __launch_bounds__(256) void k_av() {
    __shared__ float Ps[64][68];
    __shared__ float Vs[64][68];
    const int tid = threadIdx.x;
    const int tx = tid & 15, ty = tid >> 4;
    const int h  = blockIdx.x;
    const int qt = blockIdx.y * 64;
    const int b  = blockIdx.z;

    float c[4][4] = {};
    const size_t pbase = (((size_t)b*HH + h)*SS + qt) * SS;
    const float* vp = &g_v[(((size_t)b*HH + h)*SS)*HD];

    for (int k0 = 0; k0 < SS; k0 += 64) {
        for (int f = tid; f < 1024; f += 256) {
            int r = f >> 4, cq = (f & 15) << 2;
            *(float4*)&Ps[r][cq] = *(const float4*)&g_sc[pbase + (size_t)r*SS + k0 + cq];
            *(float4*)&Vs[r][cq] = *(const float4*)&vp[(size_t)(k0 + r)*HD + cq];
        }
        __syncthreads();
        #pragma unroll 8
        for (int kk = 0; kk < 64; kk++) {
            float a0 = Ps[ty*4+0][kk];
            float a1 = Ps[ty*4+1][kk];
            float a2 = Ps[ty*4+2][kk];
            float a3 = Ps[ty*4+3][kk];
            float4 v4 = *(float4*)&Vs[kk][tx*4];
            c[0][0] += a0*v4.x; c[0][1] += a0*v4.y; c[0][2] += a0*v4.z; c[0][3] += a0*v4.w;
            c[1][0] += a1*v4.x; c[1][1] += a1*v4.y; c[1][2] += a1*v4.z; c[1][3] += a1*v4.w;
            c[2][0] += a2*v4.x; c[2][1] += a2*v4.y; c[2][2] += a2*v4.z; c[2][3] += a2*v4.w;
            c[3][0] += a3*v4.x; c[3][1] += a3*v4.y; c[3][2] += a3*v4.z; c[3][3] += a3*v4.w;
        }
        __syncthreads();
    }
    #pragma unroll
    for (int i = 0; i < 4; i++) {
        int q = qt + ty*4 + i;
        float4 o; o.x = c[i][0]; o.y = c[i][1]; o.z = c[i][2]; o.w = c[i][3];
        *(float4*)&g_ao[((size_t)b*SS + q)*DD + h*64 + tx*4] = o;
    }
}

// ============================================================================
// Kernel 5: output projection.  out[m,n] = sum_k g_ao[m,k]*w_proj[n,k] + b[n]
// ============================================================================
__global__ __launch_bounds__(256) void k_proj(const float* __restrict__ w,
                                              const float* __restrict__ bias,
                                              float* __restrict__ out) {
    __shared__ float As[64][68];
    __shared__ float Bs[64][68];
    const int tid = threadIdx.x;
    const int tx = tid & 15, ty = tid >> 4;
    const int m0 = blockIdx.y * 64;
    const int n0 = blockIdx.x * 64;

    float c[4][4] = {};
    for (int k0 = 0; k0 < DD; k0 += 64) {
        for (int f = tid; f < 1024; f += 256) {
            int r = f >> 4, cq = (f & 15) << 2;
            *(float4*)&As[r][cq] = *(const float4*)&g_ao[(size_t)(m0 + r) * DD + k0 + cq];
            *(float4*)&Bs[r][cq] = *(const float4*)&w[(size_t)(n0 + r) * DD + k0 + cq];
        }
        __syncthreads();
        #pragma unroll
        for (int kk = 0; kk < 64; kk += 4) {
            float4 a[4], b4[4];
            #pragma unroll
            for (int i = 0; i < 4; i++) a[i]  = *(float4*)&As[ty*4+i][kk];
            #pragma unroll
            for (int j = 0; j < 4; j++) b4[j] = *(float4*)&Bs[tx*4+j][kk];
            #pragma unroll
            for (int i = 0; i < 4; i++)
                #pragma unroll
                for (int j = 0; j < 4; j++)
                    c[i][j] += a[i].x*b4[j].x + a[i].y*b4[j].y
                             + a[i].z*b4[j].z + a[i].w*b4[j].w;
        }
        __syncthreads();
    }
    float4 bv = *(const float4*)&bias[n0 + tx*4];
    #pragma unroll
    for (int i = 0; i < 4; i++) {
        float4 o;
        o.x = c[i][0] + bv.x; o.y = c[i][1] + bv.y;
        o.z = c[i][2] + bv.z; o.w = c[i][3] + bv.w;
        *(float4*)&out[(size_t)(m0 + ty*4 + i) * DD + n0 + tx*4] = o;
    }
}

// ============================================================================
extern "C" void kernel_launch(void* const* d_in, const int* in_sizes, int n_in,
                              void* d_out, int out_size) {
    const float* x      = (const float*)d_in[0];
    const float* w_qkv  = (const float*)d_in[1];
    const float* w_proj = (const float*)d_in[2];
    const float* b_proj = (const float*)d_in[3];
    const float* w_l    = (const float*)d_in[4];
    const float* b_l    = (const float*)d_in[5];
    const float* w_w    = (const float*)d_in[6];
    const float* b_w    = (const float*)d_in[7];
    float* out = (float*)d_out;

    cudaFuncSetAttribute(k_softmax, cudaFuncAttributeMaxDynamicSharedMemorySize, 65536);

    k_qkv   <<<dim3(QKV_N/64, NTOK/64), 256>>>(x, w_qkv);
    k_scores<<<dim3(SS/64, SS/64, BB),  256>>>(w_l, b_l);
    k_softmax<<<BB*SS, 256, 65536>>>(w_w, b_w);
    k_av    <<<dim3(HH, SS/64, BB),     256>>>();
    k_proj  <<<dim3(DD/64, NTOK/64),    256>>>(w_proj, b_proj, out);
}

// round 2
// speedup vs baseline: 1.9881x; 1.9881x over previous
#include <cuda_runtime.h>
#include <cstdint>

// Problem constants
#define BB   4
#define SS   2048
#define DD   512
#define HH   8
#define HD   64
#define NTOK (BB*SS)          // 8192
#define QKV_N (3*DD)          // 1536
#define SCALE 0.125f          // HD^-0.5

// ---------------- scratch (__device__ globals; no runtime alloc allowed) ----
static __device__ float g_q[BB*HH*SS*HD];              // 16 MB, SCALE pre-applied
static __device__ float g_k[BB*HH*SS*HD];              // 16 MB
static __device__ float g_v[BB*HH*SS*HD];              // 16 MB
static __device__ float g_sc[134217728];               // [B][H][S][S] 512 MB
static __device__ float g_ao[NTOK*DD];                 // 16 MB

// ---------------- tf32 helpers ---------------------------------------------
__device__ __forceinline__ uint32_t f2tf32(float f) {
    uint32_t u;
    asm("cvt.rna.tf32.f32 %0, %1;" : "=r"(u) : "f"(f));
    return u;
}

__device__ __forceinline__ void mma_tf32(float c[4],
                                         uint32_t a0, uint32_t a1, uint32_t a2, uint32_t a3,
                                         uint32_t b0, uint32_t b1) {
    asm volatile(
        "mma.sync.aligned.m16n8k8.row.col.f32.tf32.tf32.f32 "
        "{%0,%1,%2,%3}, {%4,%5,%6,%7}, {%8,%9}, {%0,%1,%2,%3};\n"
        : "+f"(c[0]), "+f"(c[1]), "+f"(c[2]), "+f"(c[3])
        : "r"(a0), "r"(a1), "r"(a2), "r"(a3), "r"(b0), "r"(b1));
}

// Stage a 64x64 fp32 tile (row-major, row stride `ld` floats) into tf32 smem.
// smem layout [64][68] uint32.
__device__ __forceinline__ void stage_tile(uint32_t (*S)[68], const float* __restrict__ src,
                                           size_t ld, int tid) {
    for (int f = tid; f < 1024; f += 256) {
        int r = f >> 4, c = (f & 15) << 2;
        float4 v = *(const float4*)&src[(size_t)r * ld + c];
        uint4 u;
        u.x = f2tf32(v.x); u.y = f2tf32(v.y); u.z = f2tf32(v.z); u.w = f2tf32(v.w);
        *(uint4*)&S[r][c] = u;
    }
}

// ============================================================================
// Kernel 1: QKV GEMM via tf32 MMA.  C[m,n] = sum_k x[m,k]*w_qkv[n,k]
// CTA tile 64x64, 8 warps (4x2), warp tile 16x32.
// ============================================================================
__global__ __launch_bounds__(256) void k_qkv(const float* __restrict__ x,
                                             const float* __restrict__ w) {
    __shared__ uint32_t As[64][68];
    __shared__ uint32_t Bs[64][68];
    const int tid = threadIdx.x;
    const int lane = tid & 31, warp = tid >> 5;
    const int g = lane >> 2, t = lane & 3;
    const int q0 = (warp >> 1) * 16, n0c = (warp & 1) * 32;
    const int m0 = blockIdx.y * 64;
    const int n0 = blockIdx.x * 64;

    float c[4][4] = {};
    for (int k0 = 0; k0 < DD; k0 += 64) {
        stage_tile(As, &x[(size_t)m0 * DD + k0], DD, tid);
        stage_tile(Bs, &w[(size_t)n0 * DD + k0], DD, tid);
        __syncthreads();
        #pragma unroll
        for (int kk = 0; kk < 64; kk += 8) {
            uint32_t a0 = As[q0 + g][kk + t];
            uint32_t a1 = As[q0 + g + 8][kk + t];
            uint32_t a2 = As[q0 + g][kk + t + 4];
            uint32_t a3 = As[q0 + g + 8][kk + t + 4];
            #pragma unroll
            for (int j = 0; j < 4; j++) {
                uint32_t b0 = Bs[n0c + 8*j + g][kk + t];
                uint32_t b1 = Bs[n0c + 8*j + g][kk + t + 4];
                mma_tf32(c[j], a0, a1, a2, a3, b0, b1);
            }
        }
        __syncthreads();
    }
    // epilogue scatter: n0 multiple of 64 -> single (which, h) block
    const int which = n0 >> 9;
    const int h     = (n0 >> 6) & 7;
    const int b     = m0 / SS;
    const int sbase = m0 % SS;
    float* dst = (which == 0) ? g_q : (which == 1) ? g_k : g_v;
    const float mul = (which == 0) ? SCALE : 1.0f;
    #pragma unroll
    for (int j = 0; j < 4; j++) {
        int col = n0c + 8*j + 2*t;
        float2 lo = make_float2(c[j][0]*mul, c[j][1]*mul);
        float2 hi = make_float2(c[j][2]*mul, c[j][3]*mul);
        *(float2*)&dst[(((size_t)b*HH + h)*SS + sbase + q0 + g    )*HD + col] = lo;
        *(float2*)&dst[(((size_t)b*HH + h)*SS + sbase + q0 + g + 8)*HD + col] = hi;
    }
}

// ============================================================================
// Kernel 2: scores + pre-softmax talking-heads mix (fused), tf32 MMA.
// CTA = (b, q-tile64, k-tile64); loops 8 heads, mixes into 8 g accumulators.
// ============================================================================
__global__ __launch_bounds__(256, 1) void k_scores(const float* __restrict__ wl,
                                                   const float* __restrict__ bl) {
    __shared__ uint32_t Qs[64][68];
    __shared__ uint32_t Ks[64][68];
    __shared__ float s_wl[8][8];
    __shared__ float s_bl[8];
    const int tid = threadIdx.x;
    const int lane = tid & 31, warp = tid >> 5;
    const int g = lane >> 2, t = lane & 3;
    const int q0 = (warp >> 1) * 16, n0c = (warp & 1) * 32;
    const int kt = blockIdx.x * 64;
    const int qt = blockIdx.y * 64;
    const int b  = blockIdx.z;

    if (tid < 64) s_wl[tid >> 3][tid & 7] = wl[tid];
    if (tid < 8)  s_bl[tid] = bl[tid];

    float acc[8][4][4];
    #pragma unroll
    for (int gg = 0; gg < 8; gg++)
        #pragma unroll
        for (int j = 0; j < 4; j++)
            #pragma unroll
            for (int e = 0; e < 4; e++) acc[gg][j][e] = 0.f;

    for (int h = 0; h < 8; h++) {
        __syncthreads();
        stage_tile(Qs, &g_q[(((size_t)b*HH + h)*SS + qt)*HD], HD, tid);
        stage_tile(Ks, &g_k[(((size_t)b*HH + h)*SS + kt)*HD], HD, tid);
        __syncthreads();
        float s[4][4] = {};
        #pragma unroll
        for (int kk = 0; kk < 64; kk += 8) {
            uint32_t a0 = Qs[q0 + g][kk + t];
            uint32_t a1 = Qs[q0 + g + 8][kk + t];
            uint32_t a2 = Qs[q0 + g][kk + t + 4];
            uint32_t a3 = Qs[q0 + g + 8][kk + t + 4];
            #pragma unroll
            for (int j = 0; j < 4; j++) {
                uint32_t b0 = Ks[n0c + 8*j + g][kk + t];
                uint32_t b1 = Ks[n0c + 8*j + g][kk + t + 4];
                mma_tf32(s[j], a0, a1, a2, a3, b0, b1);
            }
        }
        #pragma unroll
        for (int gg = 0; gg < 8; gg++) {
            float wv = s_wl[gg][h];
            #pragma unroll
            for (int j = 0; j < 4; j++)
                #pragma unroll
                for (int e = 0; e < 4; e++)
                    acc[gg][j][e] += wv * s[j][e];
        }
    }
    // epilogue: + b_l, store
    #pragma unroll
    for (int gg = 0; gg < 8; gg++) {
        float blv = s_bl[gg];
        size_t base = ((size_t)b*HH + gg)*SS;
        #pragma unroll
        for (int j = 0; j < 4; j++) {
            int col = kt + n0c + 8*j + 2*t;
            float2 lo = make_float2(acc[gg][j][0] + blv, acc[gg][j][1] + blv);
            float2 hi = make_float2(acc[gg][j][2] + blv, acc[gg][j][3] + blv);
            *(float2*)&g_sc[(base + qt + q0 + g    )*SS + col] = lo;
            *(float2*)&g_sc[(base + qt + q0 + g + 8)*SS + col] = hi;
        }
    }
}

// ============================================================================
// Kernel 3: softmax + post-softmax talking-heads mix (fused, in-place).
// CTA = (b, q). 8 warps; warp w softmaxes head w's 2048-row in smem, then
// all threads mix across heads with w_w (+b_w). Dynamic smem 64 KB.
// ============================================================================
__global__ __launch_bounds__(256) void k_softmax(const float* __restrict__ ww,
                                                 const float* __restrict__ bw) {
    extern __shared__ float sm[];        // [8][2048]
    __shared__ float inv_l[8];
    __shared__ float s_ww[8][8];
    __shared__ float s_bw[8];
    const int tid = threadIdx.x;
    const int b = blockIdx.x >> 11;
    const int q = blockIdx.x & 2047;

    if (tid < 64) s_ww[tid >> 3][tid & 7] = ww[tid];
    if (tid < 8)  s_bw[tid] = bw[tid];

    const size_t rowbase = (size_t)b*HH*SS*SS + (size_t)q*SS;
    for (int f = tid; f < 8*512; f += 256) {
        int h = f >> 9, c4 = (f & 511) << 2;
        *(float4*)&sm[h*SS + c4] = *(const float4*)&g_sc[rowbase + (size_t)h*SS*SS + c4];
    }
    __syncthreads();

    {
        const int h = tid >> 5, lane = tid & 31;
        float m = -1e30f;
        for (int i = lane; i < SS; i += 32) m = fmaxf(m, sm[h*SS + i]);
        #pragma unroll
        for (int o = 16; o; o >>= 1) m = fmaxf(m, __shfl_xor_sync(0xffffffffu, m, o));
        float l = 0.f;
        for (int i = lane; i < SS; i += 32) {
            float e = __expf(sm[h*SS + i] - m);
            sm[h*SS + i] = e;
            l += e;
        }
        #pragma unroll
        for (int o = 16; o; o >>= 1) l += __shfl_xor_sync(0xffffffffu, l, o);
        if (lane == 0) inv_l[h] = 1.0f / l;
    }
    __syncthreads();

    for (int i = tid; i < SS; i += 256) {
        float p[8];
        #pragma unroll
        for (int h = 0; h < 8; h++) p[h] = sm[h*SS + i] * inv_l[h];
        #pragma unroll
        for (int g = 0; g < 8; g++) {
            float o = s_bw[g];
            #pragma unroll
            for (int h = 0; h < 8; h++) o += s_ww[g][h] * p[h];
            g_sc[rowbase + (size_t)g*SS*SS + i] = o;
        }
    }
}

// ============================================================================
// Kernel 4: AV GEMM per (b, h, q-tile), tf32 MMA.
// out[q,d] = sum_k P[q,k] * V[k,d].  V staged as [k][d] (B non-transposed).
// ============================================================================
__global__ __launch_bounds__(256) void k_av() {
    __shared__ uint32_t Ps[64][68];
    __shared__ uint32_t Vs[64][68];
    const int tid = threadIdx.x;
    const int lane = tid & 31, warp = tid >> 5;
    const int g = lane >> 2, t = lane & 3;
    const int q0 = (warp >> 1) * 16, n0c = (warp & 1) * 32;
    const int h  = blockIdx.x;
    const int qt = blockIdx.y * 64;
    const int b  = blockIdx.z;

    float c[4][4] = {};
    const size_t pbase = (((size_t)b*HH + h)*SS + qt) * SS;
    const float* vp = &g_v[(((size_t)b*HH + h)*SS)*HD];

    for (int k0 = 0; k0 < SS; k0 += 64) {
        stage_tile(Ps, &g_sc[pbase + k0], SS, tid);          // P rows (q), cols (k)
        stage_tile(Vs, &vp[(size_t)k0 * HD], HD, tid);       // V rows (k), cols (d)
        __syncthreads();
        #pragma unroll
        for (int kk = 0; kk < 64; kk += 8) {
            uint32_t a0 = Ps[q0 + g][kk + t];
            uint32_t a1 = Ps[q0 + g + 8][kk + t];
            uint32_t a2 = Ps[q0 + g][kk + t + 4];
            uint32_t a3 = Ps[q0 + g + 8][kk + t + 4];
            #pragma unroll
            for (int j = 0; j < 4; j++) {
                uint32_t b0 = Vs[kk + t][n0c + 8*j + g];
                uint32_t b1 = Vs[kk + t + 4][n0c + 8*j + g];
                mma_tf32(c[j], a0, a1, a2, a3, b0, b1);
            }
        }
        __syncthreads();
    }
    #pragma unroll
    for (int j = 0; j < 4; j++) {
        int col = h*64 + n0c + 8*j + 2*t;
        float2 lo = make_float2(c[j][0], c[j][1]);
        float2 hi = make_float2(c[j][2], c[j][3]);
        *(float2*)&g_ao[((size_t)b*SS + qt + q0 + g    )*DD + col] = lo;
        *(float2*)&g_ao[((size_t)b*SS + qt + q0 + g + 8)*DD + col] = hi;
    }
}

// ============================================================================
// Kernel 5: output projection, tf32 MMA.  out = g_ao @ w_proj^T + b
// ============================================================================
__global__ __launch_bounds__(256) void k_proj(const float* __restrict__ w,
                                              const float* __restrict__ bias,
                                              float* __restrict__ out) {
    __shared__ uint32_t As[64][68];
    __shared__ uint32_t Bs[64][68];
    const int tid = threadIdx.x;
    const int lane = tid & 31, warp = tid >> 5;
    const int g = lane >> 2, t = lane & 3;
    const int q0 = (warp >> 1) * 16, n0c = (warp & 1) * 32;
    const int m0 = blockIdx.y * 64;
    const int n0 = blockIdx.x * 64;

    float c[4][4] = {};
    for (int k0 = 0; k0 < DD; k0 += 64) {
        stage_tile(As, &g_ao[(size_t)m0 * DD + k0], DD, tid);
        stage_tile(Bs, &w[(size_t)n0 * DD + k0], DD, tid);
        __syncthreads();
        #pragma unroll
        for (int kk = 0; kk < 64; kk += 8) {
            uint32_t a0 = As[q0 + g][kk + t];
            uint32_t a1 = As[q0 + g + 8][kk + t];
            uint32_t a2 = As[q0 + g][kk + t + 4];
            uint32_t a3 = As[q0 + g + 8][kk + t + 4];
            #pragma unroll
            for (int j = 0; j < 4; j++) {
                uint32_t b0 = Bs[n0c + 8*j + g][kk + t];
                uint32_t b1 = Bs[n0c + 8*j + g][kk + t + 4];
                mma_tf32(c[j], a0, a1, a2, a3, b0, b1);
            }
        }
        __syncthreads();
    }
    #pragma unroll
    for (int j = 0; j < 4; j++) {
        int col = n0 + n0c + 8*j + 2*t;
        float2 bv = *(const float2*)&bias[col];
        float2 lo = make_float2(c[j][0] + bv.x, c[j][1] + bv.y);
        float2 hi = make_float2(c[j][2] + bv.x, c[j][3] + bv.y);
        *(float2*)&out[(size_t)(m0 + q0 + g    ) * DD + col] = lo;
        *(float2*)&out[(size_t)(m0 + q0 + g + 8) * DD + col] = hi;
    }
}

// ============================================================================
extern "C" void kernel_launch(void* const* d_in, const int* in_sizes, int n_in,
                              void* d_out, int out_size) {
    const float* x      = (const float*)d_in[0];
    const float* w_qkv  = (const float*)d_in[1];
    const float* w_proj = (const float*)d_in[2];
    const float* b_proj = (const float*)d_in[3];
    const float* w_l    = (const float*)d_in[4];
    const float* b_l    = (const float*)d_in[5];
    const float* w_w    = (const float*)d_in[6];
    const float* b_w    = (const float*)d_in[7];
    float* out = (float*)d_out;

    cudaFuncSetAttribute(k_softmax, cudaFuncAttributeMaxDynamicSharedMemorySize, 65536);

    k_qkv   <<<dim3(QKV_N/64, NTOK/64), 256>>>(x, w_qkv);
    k_scores<<<dim3(SS/64, SS/64, BB),  256>>>(w_l, b_l);
    k_softmax<<<BB*SS, 256, 65536>>>(w_w, b_w);
    k_av    <<<dim3(HH, SS/64, BB),     256>>>();
    k_proj  <<<dim3(DD/64, NTOK/64),    256>>>(w_proj, b_proj, out);
}